// round 9
// baseline (speedup 1.0000x reference)
#include <cuda_runtime.h>
#include <math.h>
#include <stdint.h>

#define MAXB    64
#define MAXP    8732
#define MAXBP   (MAXB * MAXP)
#define MAXG    16
#define TILE    256
#define SM_ROWS 64
#define MAXNBLK 140

// ---------------- scratch (static device globals; zero-initialized) -------------
__device__ unsigned      g_negkey[MAXBP];
__device__ unsigned char g_mbyte[MAXBP];                 // bit7 = pos, bits0-3 = argmax g
__device__ unsigned long long g_bestkey[MAXB * MAXG];    // zero-init; reset by K3
__device__ float g_part_ce[MAXB * MAXNBLK];
__device__ float g_part_box[MAXB * MAXNBLK];
__device__ int   g_part_np[MAXB * MAXNBLK];
__device__ float g_batch_cls[MAXB];
__device__ float g_batch_box[MAXB];
__device__ int   g_batch_np[MAXB];
__device__ int   g_done;

// =====================================================================
// K1: IoU matching.  grid (B, nTiles), 256 threads, 256 priors/block.
// Per-prior argmax byte + per-GT best prior via shared tile + atomicMax.
// =====================================================================
__global__ __launch_bounds__(256) void match_kernel(
    const float* __restrict__ priors,
    const float* __restrict__ gt_boxes,
    int P, int G)
{
    __shared__ unsigned siou[MAXG * TILE];
    __shared__ float gx0[MAXG], gy0[MAXG], gx1[MAXG], gy1[MAXG], ga[MAXG];

    const int b = blockIdx.x, t = blockIdx.y;
    const int tid = threadIdx.x;

    if (tid < G) {
        float4 gv = __ldg((const float4*)gt_boxes + b * G + tid);
        gx0[tid] = gv.x; gy0[tid] = gv.y; gx1[tid] = gv.z; gy1[tid] = gv.w;
        ga[tid]  = (gv.z - gv.x) * (gv.w - gv.y);
    }
    __syncthreads();

    const int p0 = t * TILE;
    const int p  = p0 + tid;

    if (p < P) {
        float4 pv = __ldg((const float4*)priors + p);
        float px0 = pv.x - 0.5f * pv.z, py0 = pv.y - 0.5f * pv.w;
        float px1 = pv.x + 0.5f * pv.z, py1 = pv.y + 0.5f * pv.w;
        float parea = (px1 - px0) * (py1 - py0);

        float mval = -1.0f; int mg = 0;
#pragma unroll
        for (int g = 0; g < MAXG; g++) {
            if (g >= G) break;
            float ix0 = fmaxf(gx0[g], px0), iy0 = fmaxf(gy0[g], py0);
            float ix1 = fminf(gx1[g], px1), iy1 = fminf(gy1[g], py1);
            float iw = fmaxf(ix1 - ix0, 0.0f), ih = fmaxf(iy1 - iy0, 0.0f);
            float inter = iw * ih;
            float iou = inter / (ga[g] + parea - inter);     // IEEE div (matches ref)
            if (iou > mval) { mval = iou; mg = g; }          // first-g tie-break
            siou[g * TILE + tid] = __float_as_uint(iou);     // iou>=0 => ordered bits
        }
        g_mbyte[b * P + p] =
            (unsigned char)(mg | ((mval >= 0.5f) ? 0x80 : 0));
    } else {
#pragma unroll
        for (int g = 0; g < MAXG; g++) {
            if (g >= G) break;
            siou[g * TILE + tid] = 0u;
        }
    }
    __syncthreads();

    const int warp = tid >> 5, lane = tid & 31;
#pragma unroll
    for (int gg = warp; gg < MAXG; gg += 8) {
        if (gg >= G) break;
        unsigned long long best = 0ull;
#pragma unroll
        for (int i = 0; i < TILE / 32; i++) {
            const int c = lane + 32 * i;
            unsigned bits = siou[gg * TILE + c];
            unsigned long long key =
                ((unsigned long long)bits << 32) |
                (unsigned long long)(0xFFFFFFFFu - (unsigned)(p0 + c));
            if (key > best) best = key;                      // lower p wins ties
        }
#pragma unroll
        for (int o = 16; o > 0; o >>= 1) {
            unsigned long long other = __shfl_down_sync(0xffffffffu, best, o);
            if (other > best) best = other;
        }
        if (lane == 0) atomicMax(&g_bestkey[b * MAXG + gg], best);
    }
}

// =====================================================================
// K2: softmax + apply, direct-LDG (no smem staging).  grid (nblk, B),
// 256 threads, 64 rows/block (warp w owns rows w*8..w*8+7, pair-loaded
// with 6 outstanding LDGs).  Pre-pass resolves overrides/labels/box.
// =====================================================================
__global__ __launch_bounds__(256) void softmax_apply(
    const float* __restrict__ logits,
    const float* __restrict__ priors,
    const float* __restrict__ box_reg,
    const float* __restrict__ gt_boxes,
    const int*   __restrict__ gt_labels,
    int P, int C, int G, int nblk)
{
    __shared__ float gx0[MAXG], gy0[MAXG], gx1[MAXG], gy1[MAXG];
    __shared__ int   glab[MAXG], bp[MAXG];
    __shared__ int   s_lab[SM_ROWS];
    __shared__ float s_box[SM_ROWS];
    __shared__ float wce[8];

    const int b  = blockIdx.y;
    const int r0 = blockIdx.x * SM_ROWS;
    const int R  = min(SM_ROWS, P - r0);
    const int tid = threadIdx.x;
    const int warp = tid >> 5, lane = tid & 31;

    if (tid < G) {
        float4 gv = __ldg((const float4*)gt_boxes + b * G + tid);
        gx0[tid] = gv.x; gy0[tid] = gv.y; gx1[tid] = gv.z; gy1[tid] = gv.w;
        glab[tid] = gt_labels[b * G + tid];
        bp[tid] = (int)(0xFFFFFFFFu -
                        (unsigned)(g_bestkey[b * MAXG + tid] & 0xFFFFFFFFull));
    }
    __syncthreads();

    // pre-pass: one thread per row -> resolve override, label, box loss
    if (tid < R) {
        const int p = r0 + tid;
        unsigned char mb = g_mbyte[b * P + p];
        int mg  = mb & 15;
        int pos = mb >> 7;
#pragma unroll
        for (int g = 0; g < MAXG; g++) {          // ascending: last-GT-wins (.set)
            if (g >= G) break;
            if (bp[g] == p) { mg = g; pos = 1; }
        }
        float boxv = 0.0f;
        int lab = 0;
        if (pos) {
            lab = glab[mg];
            float4 pv = __ldg((const float4*)priors + p);
            float bx0 = gx0[mg], by0 = gy0[mg], bx1 = gx1[mg], by1 = gy1[mg];
            float t0 = ((bx0 + bx1) * 0.5f - pv.x) / (0.1f * pv.z);
            float t1 = ((by0 + by1) * 0.5f - pv.y) / (0.1f * pv.w);
            float t2 = __logf((bx1 - bx0) / pv.z) / 0.2f;
            float t3 = __logf((by1 - by0) / pv.w) / 0.2f;
            float4 br = __ldg((const float4*)box_reg + (b * P + p));
            float d0 = fabsf(br.x - t0), d1 = fabsf(br.y - t1);
            float d2 = fabsf(br.z - t2), d3 = fabsf(br.w - t3);
            boxv  = (d0 < 1.0f) ? 0.5f * d0 * d0 : d0 - 0.5f;
            boxv += (d1 < 1.0f) ? 0.5f * d1 * d1 : d1 - 0.5f;
            boxv += (d2 < 1.0f) ? 0.5f * d2 * d2 : d2 - 0.5f;
            boxv += (d3 < 1.0f) ? 0.5f * d3 * d3 : d3 - 0.5f;
        }
        s_lab[tid] = lab;
        s_box[tid] = boxv;
    }
    __syncthreads();

    // main: row pairs, 6 outstanding LDGs, shuffle lse, negkey / CE
    float ce = 0.0f;
    const int rbase = warp * 8;                    // this warp's 8 rows (local)
#pragma unroll
    for (int jj = 0; jj < 4; jj++) {
        const int rA = rbase + jj * 2;
        const int rB = rA + 1;
        const bool vA = rA < R, vB = rB < R;

        const float* rpA = logits + ((size_t)b * P + r0 + rA) * C;
        const float* rpB = rpA + C;
        float a0 = 0.f, a1 = 0.f, a2 = 0.f, b0 = 0.f, b1 = 0.f, b2 = 0.f;
        if (vA) {
            a0 = __ldg(rpA + lane);
            if (lane + 32 < C) a1 = __ldg(rpA + lane + 32);
            if (lane + 64 < C) a2 = __ldg(rpA + lane + 64);
        }
        if (vB) {
            b0 = __ldg(rpB + lane);
            if (lane + 32 < C) b1 = __ldg(rpB + lane + 32);
            if (lane + 64 < C) b2 = __ldg(rpB + lane + 64);
        }

        float sA = 0.f, sB = 0.f;
        if (vA) {
            sA = __expf(a0);
            if (lane + 32 < C) sA += __expf(a1);
            if (lane + 64 < C) sA += __expf(a2);
        }
        if (vB) {
            sB = __expf(b0);
            if (lane + 32 < C) sB += __expf(b1);
            if (lane + 64 < C) sB += __expf(b2);
        }
#pragma unroll
        for (int o = 16; o > 0; o >>= 1) {
            sA += __shfl_xor_sync(0xffffffffu, sA, o);
            sB += __shfl_xor_sync(0xffffffffu, sB, o);
        }

        if (vA) {
            const int lab = s_lab[rA];
            if (lab > 0) {
                float xv = (lab < 32) ? a0 : ((lab < 64) ? a1 : a2);
                float xl = __shfl_sync(0xffffffffu, xv, lab & 31);
                if (lane == 0) {
                    ce += __logf(sA) - xl;
                    g_negkey[b * P + r0 + rA] = 0u;
                }
            } else if (lane == 0) {
                g_negkey[b * P + r0 + rA] =
                    __float_as_uint(fmaxf(__logf(sA) - a0, 0.0f));
            }
        }
        if (vB) {
            const int lab = s_lab[rB];
            if (lab > 0) {
                float xv = (lab < 32) ? b0 : ((lab < 64) ? b1 : b2);
                float xl = __shfl_sync(0xffffffffu, xv, lab & 31);
                if (lane == 0) {
                    ce += __logf(sB) - xl;
                    g_negkey[b * P + r0 + rB] = 0u;
                }
            } else if (lane == 0) {
                g_negkey[b * P + r0 + rB] =
                    __float_as_uint(fmaxf(__logf(sB) - b0, 0.0f));
            }
        }
    }
    if (lane == 0) wce[warp] = ce;
    __syncthreads();

    // block partials: box/np from s_box/s_lab (warp 0), ce from wce
    if (warp == 0) {
        float boxv = 0.0f; int np = 0;
        if (lane < R)      { boxv += s_box[lane];      np += (s_lab[lane] > 0); }
        if (lane + 32 < R) { boxv += s_box[lane + 32]; np += (s_lab[lane + 32] > 0); }
#pragma unroll
        for (int o = 16; o > 0; o >>= 1) {
            boxv += __shfl_down_sync(0xffffffffu, boxv, o);
            np   += __shfl_down_sync(0xffffffffu, np, o);
        }
        if (lane == 0) {
            float c = 0.0f;
#pragma unroll
            for (int w2 = 0; w2 < 8; w2++) c += wce[w2];
            const int pi = b * nblk + blockIdx.x;
            g_part_ce[pi]  = c;
            g_part_box[pi] = boxv;
            g_part_np[pi]  = np;
        }
    }
}

// =====================================================================
// K3: per-batch exact top-k sum (3-pass histogram select, warp-
// aggregated atomics) + bestkey reset + ticket finalize.
// =====================================================================
__global__ __launch_bounds__(1024) void topk_kernel(
    float* __restrict__ out, int P, int B, int G, int nblk)
{
    const int b = blockIdx.x;
    const int tid = threadIdx.x;
    const int NT = 1024;
    const int lane = tid & 31, warp = tid >> 5;

    __shared__ unsigned sk[MAXP];
    __shared__ int   hist[4096];
    __shared__ int   suf[256];
    __shared__ float wsf[32], wsf2[32];
    __shared__ int   wsi[32];
    __shared__ int   f_bucket, f_above, sh_k, sh_last;
    __shared__ float sh_ce;

    // stage keys (batched, MLP=3)
    {
        const int nv = P >> 2;
        const uint4* nk4 = (const uint4*)(g_negkey + b * P);
        uint4 kv[3]; bool gd[3];
#pragma unroll
        for (int kk = 0; kk < 3; kk++) {
            const int i = tid + kk * NT;
            gd[kk] = i < nv;
            if (gd[kk]) kv[kk] = __ldg(&nk4[i]);
        }
#pragma unroll
        for (int kk = 0; kk < 3; kk++) {
            const int i = tid + kk * NT;
            if (gd[kk]) {
                sk[i * 4 + 0] = kv[kk].x; sk[i * 4 + 1] = kv[kk].y;
                sk[i * 4 + 2] = kv[kk].z; sk[i * 4 + 3] = kv[kk].w;
            }
        }
        for (int i = (nv << 2) + tid; i < P; i += NT) sk[i] = g_negkey[b * P + i];
    }
    if (tid < G) g_bestkey[b * MAXG + tid] = 0ull;   // reset for next replay

    // partials
    float ce = 0.0f, bx = 0.0f; int np = 0;
    for (int i = tid; i < nblk; i += NT) {
        ce += g_part_ce[b * nblk + i];
        bx += g_part_box[b * nblk + i];
        np += g_part_np[b * nblk + i];
    }
#pragma unroll
    for (int o = 16; o > 0; o >>= 1) {
        ce += __shfl_down_sync(0xffffffffu, ce, o);
        bx += __shfl_down_sync(0xffffffffu, bx, o);
        np += __shfl_down_sync(0xffffffffu, np, o);
    }
    if (lane == 0) { wsf[warp] = ce; wsf2[warp] = bx; wsi[warp] = np; }
    __syncthreads();
    if (warp == 0) {
        float c2 = wsf[lane], b2 = wsf2[lane];
        int n2 = wsi[lane];
#pragma unroll
        for (int o = 16; o > 0; o >>= 1) {
            c2 += __shfl_down_sync(0xffffffffu, c2, o);
            b2 += __shfl_down_sync(0xffffffffu, b2, o);
            n2 += __shfl_down_sync(0xffffffffu, n2, o);
        }
        if (lane == 0) {
            int k = n2 * 3; if (k > P) k = P;
            sh_k = k; sh_ce = c2;
            g_batch_box[b] = b2;
            g_batch_np[b]  = n2;
        }
    }
    __syncthreads();
    int k = sh_k;

    float cls = sh_ce;
    if (k > 0) {
        unsigned prefix = 0;
        const int shifts[3] = {20, 8, 0};
        const int bitsA[3]  = {12, 12, 8};
        const int iters = (P + NT - 1) / NT;
#pragma unroll
        for (int ps = 0; ps < 3; ps++) {
            const int shift = shifts[ps];
            const int nbits = bitsA[ps];
            const int nb = 1 << nbits;
            const unsigned himask = (unsigned)(~((1ull << (shift + nbits)) - 1ull));

            for (int i = tid; i < nb; i += NT) hist[i] = 0;
            __syncthreads();

            for (int it = 0; it < iters; it++) {
                const int p = tid + it * NT;
                unsigned key = (p < P) ? sk[p] : 0u;
                const bool act = (p < P) && ((key & himask) == prefix);
                unsigned bkt = act ? ((key >> shift) & (nb - 1)) : 0xFFFFFFFFu;
                unsigned mm = __match_any_sync(0xffffffffu, bkt);
                if (act && ((int)(__ffs(mm) - 1) == lane))
                    atomicAdd(&hist[bkt], __popc(mm));
            }
            __syncthreads();

            const int cw = nb >> 8;
            int cs = 0;
            if (tid < 256)
                for (int i = 0; i < cw; i++) cs += hist[tid * cw + i];
            int v = cs;
#pragma unroll
            for (int o = 1; o < 32; o <<= 1) {
                int u = __shfl_down_sync(0xffffffffu, v, o);
                if (lane + o < 32) v += u;
            }
            if (tid < 256 && lane == 0) wsi[warp] = v;
            __syncthreads();
            if (tid < 256) {
                int off = 0;
                for (int w2 = warp + 1; w2 < 8; w2++) off += wsi[w2];
                suf[tid] = v + off;                          // inclusive suffix
            }
            __syncthreads();
            if (tid < 256) {
                int running = suf[tid] - cs;                 // strictly above chunk
                for (int i = cw - 1; i >= 0; i--) {
                    int c = hist[tid * cw + i];
                    if (c > 0 && running < k && running + c >= k) {
                        f_bucket = tid * cw + i;             // unique writer
                        f_above  = running;
                    }
                    running += c;
                }
            }
            __syncthreads();
            prefix |= ((unsigned)f_bucket) << shift;
            k -= f_above;
            __syncthreads();
        }

        float ss = 0.0f;
        for (int p = tid; p < P; p += NT) {
            unsigned key = sk[p];
            if (key > prefix) ss += __uint_as_float(key);
        }
#pragma unroll
        for (int o = 16; o > 0; o >>= 1) ss += __shfl_down_sync(0xffffffffu, ss, o);
        if (lane == 0) wsf[warp] = ss;
        __syncthreads();
        if (warp == 0) {
            float s2 = wsf[lane];
#pragma unroll
            for (int o = 16; o > 0; o >>= 1) s2 += __shfl_down_sync(0xffffffffu, s2, o);
            if (lane == 0) wsf[0] = s2;
        }
        __syncthreads();
        cls += wsf[0] + (float)k * __uint_as_float(prefix);  // residual ties
    }

    if (tid == 0) {
        g_batch_cls[b] = cls;
        __threadfence();
        int v = atomicAdd(&g_done, 1);
        sh_last = (v == B - 1) ? 1 : 0;
    }
    __syncthreads();

    if (sh_last) {
        float box = 0.0f, ctot = 0.0f; int npos = 0;
        for (int i = tid; i < B; i += NT) {
            box  += *(volatile float*)&g_batch_box[i];
            ctot += *(volatile float*)&g_batch_cls[i];
            npos += *(volatile int*)&g_batch_np[i];
        }
#pragma unroll
        for (int o = 16; o > 0; o >>= 1) {
            box  += __shfl_down_sync(0xffffffffu, box, o);
            ctot += __shfl_down_sync(0xffffffffu, ctot, o);
            npos += __shfl_down_sync(0xffffffffu, npos, o);
        }
        if (lane == 0) { wsf[warp] = box; wsf2[warp] = ctot; wsi[warp] = npos; }
        __syncthreads();
        if (warp == 0) {
            float b2 = wsf[lane], c2 = wsf2[lane];
            int n2 = wsi[lane];
#pragma unroll
            for (int o = 16; o > 0; o >>= 1) {
                b2 += __shfl_down_sync(0xffffffffu, b2, o);
                c2 += __shfl_down_sync(0xffffffffu, c2, o);
                n2 += __shfl_down_sync(0xffffffffu, n2, o);
            }
            if (lane == 0) {
                float inv = 1.0f / (float)n2;
                out[0] = b2 * inv;
                out[1] = c2 * inv;
                g_done = 0;                                  // self-reset for replay
            }
        }
    }
}

// =====================================================================
extern "C" void kernel_launch(void* const* d_in, const int* in_sizes, int n_in,
                              void* d_out, int out_size)
{
    const float* priors = (const float*)d_in[0];
    const float* logits = (const float*)d_in[1];
    const float* boxreg = (const float*)d_in[2];
    const float* gtb    = (const float*)d_in[3];
    const int*   gtl    = (const int*)d_in[4];

    const int P = in_sizes[0] / 4;
    const int B = in_sizes[2] / (4 * P);
    const int C = in_sizes[1] / (B * P);
    const int G = in_sizes[4] / B;

    const int nTiles = (P + TILE - 1) / TILE;
    const int nblk   = (P + SM_ROWS - 1) / SM_ROWS;

    dim3 gm(B, nTiles);
    match_kernel<<<gm, 256>>>(priors, gtb, P, G);

    dim3 gs(nblk, B);
    softmax_apply<<<gs, 256>>>(logits, priors, boxreg, gtb, gtl, P, C, G, nblk);

    topk_kernel<<<B, 1024>>>((float*)d_out, P, B, G, nblk);
}